// round 1
// baseline (speedup 1.0000x reference)
#include <cuda_runtime.h>

// Problem constants (fixed for this checkpoint)
#define S 4096
#define I 1024
#define C 8
#define H 8
#define NSB 8
#define SB (S / NSB)   // 512
#define TI 16

// Scratch (static __device__ arrays per harness rules)
__device__ float2 g_kv[S * I];            // interleaved k,v per (s,i)  ~33.5 MB
__device__ float  g_qpart[NSB * I * 9];   // per-s-block partial {qsum[8], msum}
__device__ float  g_o[I * H];             // attention output per (i,h)

// ---------------------------------------------------------------------------
// K1: per (s,i) layernorm -> k,v scalars (coalesced float2 store) + masked
//     mean-pool partials per (s_block, i). Deterministic, no atomics.
// ---------------------------------------------------------------------------
__global__ __launch_bounds__(256) void k1(const float* __restrict__ m,
                                          const float* __restrict__ mask,
                                          const float* __restrict__ lnw,
                                          const float* __restrict__ lnb,
                                          const float* __restrict__ wk,
                                          const float* __restrict__ wv)
{
    const int il = threadIdx.x & (TI - 1);
    const int sl = threadIdx.x >> 4;          // 0..15
    const int i0 = blockIdx.x * TI;
    const int s0 = blockIdx.y * SB;
    const int i  = i0 + il;

    float LW[C], LB[C], WK[C], WV[C];
#pragma unroll
    for (int c = 0; c < C; ++c) { LW[c] = lnw[c]; LB[c] = lnb[c]; WK[c] = wk[c]; WV[c] = wv[c]; }

    float qs[C];
#pragma unroll
    for (int c = 0; c < C; ++c) qs[c] = 0.f;
    float ms = 0.f;

#pragma unroll 2
    for (int j = 0; j < SB / 16; ++j) {
        const int s = s0 + sl + j * 16;
        const float4* mp = (const float4*)(m + ((size_t)s * I + i) * C);
        float4 a = mp[0], b = mp[1];
        float x[C] = {a.x, a.y, a.z, a.w, b.x, b.y, b.z, b.w};

        float mu = 0.f;
#pragma unroll
        for (int c = 0; c < C; ++c) mu += x[c];
        mu *= (1.0f / C);
        float var = 0.f;
#pragma unroll
        for (int c = 0; c < C; ++c) { float d = x[c] - mu; var += d * d; }
        var *= (1.0f / C);
        const float rstd = rsqrtf(var + 1e-5f);
        const float mk = mask[(size_t)s * I + i];

        float kk = 0.f, vv = 0.f;
#pragma unroll
        for (int c = 0; c < C; ++c) {
            float mn = (x[c] - mu) * rstd * LW[c] + LB[c];
            kk += mn * WK[c];
            vv += mn * WV[c];
            qs[c] += mn * mk;
        }
        ms += mk;
        g_kv[(size_t)s * I + i] = make_float2(kk, vv);
    }

    // reduce masked-pool partials over the 16 s-lanes per i
    __shared__ float red[16][TI][9];
#pragma unroll
    for (int c = 0; c < C; ++c) red[sl][il][c] = qs[c];
    red[sl][il][8] = ms;
    __syncthreads();

    const int t = threadIdx.x;
    if (t < TI * 9) {
        const int ril = t / 9, rc = t % 9;
        float sum = 0.f;
#pragma unroll
        for (int r = 0; r < 16; ++r) sum += red[r][ril][rc];
        g_qpart[((size_t)blockIdx.y * I + (i0 + ril)) * 9 + rc] = sum;
    }
}

// ---------------------------------------------------------------------------
// K2: per i (8 per CTA): finalize q = pooled@wq, two-pass softmax over s
//     (max pass + exp/sum pass), o[i][h] = sum(p*v)/sum(p).
//     k,v read from just-written L2-resident scratch.
// ---------------------------------------------------------------------------
__global__ __launch_bounds__(256) void k2(const float* __restrict__ mask,
                                          const float* __restrict__ wq)
{
    const int t  = threadIdx.x;
    const int i0 = blockIdx.x * 8;

    __shared__ float qp[8][9];
    __shared__ float shq[8][8];
    __shared__ float shmax[8][8];
    __shared__ float sred[256 * 16];

    if (t < 72) {
        const int il = t / 9, c = t % 9;
        float sum = 0.f;
#pragma unroll
        for (int nb = 0; nb < NSB; ++nb)
            sum += g_qpart[((size_t)nb * I + i0 + il) * 9 + c];
        qp[il][c] = sum;
    }
    __syncthreads();
    if (t < 64) {
        const int il = t >> 3, h = t & 7;
        const float inv = 1.0f / (qp[il][8] + 1e-5f);
        float q = 0.f;
#pragma unroll
        for (int c = 0; c < C; ++c) q += (qp[il][c] * inv) * wq[h * C + c];
        shq[il][h] = q;   // c_h^-0.5 = 1
    }
    __syncthreads();

    const int il = t & 7;
    const int sl = t >> 3;        // 0..31
    const int i  = i0 + il;

    float q[H];
#pragma unroll
    for (int h = 0; h < H; ++h) q[h] = shq[il][h];

    // pass A: max
    float mx[H];
#pragma unroll
    for (int h = 0; h < H; ++h) mx[h] = -1e30f;
    for (int s = sl; s < S; s += 32) {
        const float2 kv = g_kv[(size_t)s * I + i];
        const float bias = 1e9f * (mask[(size_t)s * I + i] - 1.0f);
#pragma unroll
        for (int h = 0; h < H; ++h) mx[h] = fmaxf(mx[h], q[h] * kv.x + bias);
    }
#pragma unroll
    for (int h = 0; h < H; ++h) sred[t * 8 + h] = mx[h];
    __syncthreads();
    if (t < 64) {
        const int ril = t >> 3, h = t & 7;
        float M = -1e30f;
#pragma unroll
        for (int r = 0; r < 32; ++r) M = fmaxf(M, sred[(ril + 8 * r) * 8 + h]);
        shmax[ril][h] = M;
    }
    __syncthreads();
    float M[H];
#pragma unroll
    for (int h = 0; h < H; ++h) M[h] = shmax[il][h];

    // pass B: exp/sum/weighted-v
    float sm[H], ov[H];
#pragma unroll
    for (int h = 0; h < H; ++h) { sm[h] = 0.f; ov[h] = 0.f; }
    for (int s = sl; s < S; s += 32) {
        const float2 kv = g_kv[(size_t)s * I + i];
        const float bias = 1e9f * (mask[(size_t)s * I + i] - 1.0f);
#pragma unroll
        for (int h = 0; h < H; ++h) {
            const float p = __expf(q[h] * kv.x + bias - M[h]);
            sm[h] += p;
            ov[h] += p * kv.y;
        }
    }
    __syncthreads();   // sred reuse safe: prior reads completed before shmax sync
#pragma unroll
    for (int h = 0; h < H; ++h) { sred[t * 16 + h] = sm[h]; sred[t * 16 + 8 + h] = ov[h]; }
    __syncthreads();
    if (t < 64) {
        const int ril = t >> 3, h = t & 7;
        float Ssum = 0.f, OV = 0.f;
#pragma unroll
        for (int r = 0; r < 32; ++r) {
            Ssum += sred[(ril + 8 * r) * 16 + h];
            OV   += sred[(ril + 8 * r) * 16 + 8 + h];
        }
        g_o[(i0 + ril) * H + h] = OV / Ssum;
    }
}

// ---------------------------------------------------------------------------
// K3: per (s,i): recompute layernorm, gate g = sigmoid(mn@wg + bg),
//     out = (o[i]*g) @ wo^T + bo. Grid stride is a multiple of I so each
//     thread's i (and o[i][:]) is loop-invariant.
// ---------------------------------------------------------------------------
#define K3_BLOCKS 304   // 304*256 = 77824 = 76*1024 (multiple of I)

__global__ __launch_bounds__(256) void k3(const float* __restrict__ m,
                                          const float* __restrict__ lnw,
                                          const float* __restrict__ lnb,
                                          const float* __restrict__ wg,
                                          const float* __restrict__ bg,
                                          const float* __restrict__ wo,
                                          const float* __restrict__ bo,
                                          float* __restrict__ out)
{
    const int gt = blockIdx.x * 256 + threadIdx.x;
    const int i  = gt & (I - 1);

    float LW[C], LB[C], BG[H], BO[C], WG[H][C], WO[C][H];
#pragma unroll
    for (int c = 0; c < C; ++c) { LW[c] = lnw[c]; LB[c] = lnb[c]; BO[c] = bo[c]; }
#pragma unroll
    for (int h = 0; h < H; ++h) {
        BG[h] = bg[h];
#pragma unroll
        for (int c = 0; c < C; ++c) WG[h][c] = wg[h * C + c];
    }
#pragma unroll
    for (int c = 0; c < C; ++c)
#pragma unroll
        for (int h = 0; h < H; ++h) WO[c][h] = wo[c * H + h];

    float O[H];
#pragma unroll
    for (int h = 0; h < H; ++h) O[h] = g_o[i * H + h];

    const size_t stride = (size_t)K3_BLOCKS * 256;
    for (size_t p = gt; p < (size_t)S * I; p += stride) {
        const float4* mp = (const float4*)(m + p * C);
        float4 a = mp[0], b = mp[1];
        float x[C] = {a.x, a.y, a.z, a.w, b.x, b.y, b.z, b.w};

        float mu = 0.f;
#pragma unroll
        for (int c = 0; c < C; ++c) mu += x[c];
        mu *= (1.0f / C);
        float var = 0.f;
#pragma unroll
        for (int c = 0; c < C; ++c) { float d = x[c] - mu; var += d * d; }
        var *= (1.0f / C);
        const float rstd = rsqrtf(var + 1e-5f);

        float mn[C];
#pragma unroll
        for (int c = 0; c < C; ++c) mn[c] = (x[c] - mu) * rstd * LW[c] + LB[c];

        float acc[C];
#pragma unroll
        for (int c = 0; c < C; ++c) acc[c] = BO[c];

#pragma unroll
        for (int h = 0; h < H; ++h) {
            float z = BG[h];
#pragma unroll
            for (int c = 0; c < C; ++c) z += mn[c] * WG[h][c];
            const float g = 1.0f / (1.0f + __expf(-z));
            const float th = O[h] * g;
#pragma unroll
            for (int c = 0; c < C; ++c) acc[c] += th * WO[c][h];
        }

        float4 r0 = make_float4(acc[0], acc[1], acc[2], acc[3]);
        float4 r1 = make_float4(acc[4], acc[5], acc[6], acc[7]);
        float4* op = (float4*)(out + p * C);
        op[0] = r0;
        op[1] = r1;
    }
}

// ---------------------------------------------------------------------------
extern "C" void kernel_launch(void* const* d_in, const int* in_sizes, int n_in,
                              void* d_out, int out_size)
{
    const float* m    = (const float*)d_in[0];
    const float* mask = (const float*)d_in[1];
    const float* lnw  = (const float*)d_in[2];
    const float* lnb  = (const float*)d_in[3];
    const float* wq   = (const float*)d_in[4];
    const float* wk   = (const float*)d_in[5];
    const float* wv   = (const float*)d_in[6];
    const float* wg   = (const float*)d_in[7];
    const float* bg   = (const float*)d_in[8];
    const float* wo   = (const float*)d_in[9];
    const float* bo   = (const float*)d_in[10];
    float* out = (float*)d_out;

    dim3 g1(I / TI, NSB);
    k1<<<g1, 256>>>(m, mask, lnw, lnb, wk, wv);
    k2<<<I / 8, 256>>>(mask, wq);
    k3<<<K3_BLOCKS, 256>>>(m, lnw, lnb, wg, bg, wo, bo, out);
}

// round 2
// speedup vs baseline: 1.0116x; 1.0116x over previous
#include <cuda_runtime.h>

// Problem constants (fixed for this checkpoint)
#define S 4096
#define I 1024
#define C 8
#define H 8
#define NSB 8
#define SB (S / NSB)   // 512
#define TI 16

// Scratch (static __device__ arrays per harness rules)
__device__ float2 g_kv[S * I];            // interleaved k,v per (s,i)  ~33.5 MB
__device__ float  g_qpart[NSB * I * 9];   // per-s-block partial {qsum[8], msum}
__device__ float  g_o[I * H];             // attention output per (i,h)

// ---------------------------------------------------------------------------
// K1: per (s,i) layernorm -> k,v scalars (coalesced float2 store) + masked
//     mean-pool partials per (s_block, i). Deterministic, no atomics.
// ---------------------------------------------------------------------------
__global__ __launch_bounds__(256) void k1(const float* __restrict__ m,
                                          const float* __restrict__ mask,
                                          const float* __restrict__ lnw,
                                          const float* __restrict__ lnb,
                                          const float* __restrict__ wk,
                                          const float* __restrict__ wv)
{
    const int il = threadIdx.x & (TI - 1);
    const int sl = threadIdx.x >> 4;          // 0..15
    const int i0 = blockIdx.x * TI;
    const int s0 = blockIdx.y * SB;
    const int i  = i0 + il;

    float LW[C], LB[C], WK[C], WV[C];
#pragma unroll
    for (int c = 0; c < C; ++c) { LW[c] = lnw[c]; LB[c] = lnb[c]; WK[c] = wk[c]; WV[c] = wv[c]; }

    float qs[C];
#pragma unroll
    for (int c = 0; c < C; ++c) qs[c] = 0.f;
    float ms = 0.f;

#pragma unroll 2
    for (int j = 0; j < SB / 16; ++j) {
        const int s = s0 + sl + j * 16;
        const float4* mp = (const float4*)(m + ((size_t)s * I + i) * C);
        float4 a = mp[0], b = mp[1];
        float x[C] = {a.x, a.y, a.z, a.w, b.x, b.y, b.z, b.w};

        float mu = 0.f;
#pragma unroll
        for (int c = 0; c < C; ++c) mu += x[c];
        mu *= (1.0f / C);
        float var = 0.f;
#pragma unroll
        for (int c = 0; c < C; ++c) { float d = x[c] - mu; var += d * d; }
        var *= (1.0f / C);
        const float rstd = rsqrtf(var + 1e-5f);
        const float mk = mask[(size_t)s * I + i];

        float kk = 0.f, vv = 0.f;
#pragma unroll
        for (int c = 0; c < C; ++c) {
            float mn = (x[c] - mu) * rstd * LW[c] + LB[c];
            kk += mn * WK[c];
            vv += mn * WV[c];
            qs[c] += mn * mk;
        }
        ms += mk;
        g_kv[(size_t)s * I + i] = make_float2(kk, vv);
    }

    // reduce masked-pool partials over the 16 s-lanes per i
    __shared__ float red[16][TI][9];
#pragma unroll
    for (int c = 0; c < C; ++c) red[sl][il][c] = qs[c];
    red[sl][il][8] = ms;
    __syncthreads();

    const int t = threadIdx.x;
    if (t < TI * 9) {
        const int ril = t / 9, rc = t % 9;
        float sum = 0.f;
#pragma unroll
        for (int r = 0; r < 16; ++r) sum += red[r][ril][rc];
        g_qpart[((size_t)blockIdx.y * I + (i0 + ril)) * 9 + rc] = sum;
    }
}

// ---------------------------------------------------------------------------
// K2: per i (8 per CTA): finalize q = pooled@wq, two-pass softmax over s
//     (max pass + exp/sum pass), o[i][h] = sum(p*v)/sum(p).
//     k,v read from just-written L2-resident scratch.
// ---------------------------------------------------------------------------
__global__ __launch_bounds__(256) void k2(const float* __restrict__ mask,
                                          const float* __restrict__ wq)
{
    const int t  = threadIdx.x;
    const int i0 = blockIdx.x * 8;

    __shared__ float qp[8][9];
    __shared__ float shq[8][8];
    __shared__ float shmax[8][8];
    __shared__ float sred[256 * 16];

    if (t < 72) {
        const int il = t / 9, c = t % 9;
        float sum = 0.f;
#pragma unroll
        for (int nb = 0; nb < NSB; ++nb)
            sum += g_qpart[((size_t)nb * I + i0 + il) * 9 + c];
        qp[il][c] = sum;
    }
    __syncthreads();
    if (t < 64) {
        const int il = t >> 3, h = t & 7;
        const float inv = 1.0f / (qp[il][8] + 1e-5f);
        float q = 0.f;
#pragma unroll
        for (int c = 0; c < C; ++c) q += (qp[il][c] * inv) * wq[h * C + c];
        shq[il][h] = q;   // c_h^-0.5 = 1
    }
    __syncthreads();

    const int il = t & 7;
    const int sl = t >> 3;        // 0..31
    const int i  = i0 + il;

    float q[H];
#pragma unroll
    for (int h = 0; h < H; ++h) q[h] = shq[il][h];

    // pass A: max
    float mx[H];
#pragma unroll
    for (int h = 0; h < H; ++h) mx[h] = -1e30f;
    for (int s = sl; s < S; s += 32) {
        const float2 kv = g_kv[(size_t)s * I + i];
        const float bias = 1e9f * (mask[(size_t)s * I + i] - 1.0f);
#pragma unroll
        for (int h = 0; h < H; ++h) mx[h] = fmaxf(mx[h], q[h] * kv.x + bias);
    }
#pragma unroll
    for (int h = 0; h < H; ++h) sred[t * 8 + h] = mx[h];
    __syncthreads();
    if (t < 64) {
        const int ril = t >> 3, h = t & 7;
        float M = -1e30f;
#pragma unroll
        for (int r = 0; r < 32; ++r) M = fmaxf(M, sred[(ril + 8 * r) * 8 + h]);
        shmax[ril][h] = M;
    }
    __syncthreads();
    float M[H];
#pragma unroll
    for (int h = 0; h < H; ++h) M[h] = shmax[il][h];

    // pass B: exp/sum/weighted-v
    float sm[H], ov[H];
#pragma unroll
    for (int h = 0; h < H; ++h) { sm[h] = 0.f; ov[h] = 0.f; }
    for (int s = sl; s < S; s += 32) {
        const float2 kv = g_kv[(size_t)s * I + i];
        const float bias = 1e9f * (mask[(size_t)s * I + i] - 1.0f);
#pragma unroll
        for (int h = 0; h < H; ++h) {
            const float p = __expf(q[h] * kv.x + bias - M[h]);
            sm[h] += p;
            ov[h] += p * kv.y;
        }
    }
    __syncthreads();   // sred reuse safe: prior reads completed before shmax sync
#pragma unroll
    for (int h = 0; h < H; ++h) { sred[t * 16 + h] = sm[h]; sred[t * 16 + 8 + h] = ov[h]; }
    __syncthreads();
    if (t < 64) {
        const int ril = t >> 3, h = t & 7;
        float Ssum = 0.f, OV = 0.f;
#pragma unroll
        for (int r = 0; r < 32; ++r) {
            Ssum += sred[(ril + 8 * r) * 16 + h];
            OV   += sred[(ril + 8 * r) * 16 + 8 + h];
        }
        g_o[(i0 + ril) * H + h] = OV / Ssum;
    }
}

// ---------------------------------------------------------------------------
// K3: per (s,i): recompute layernorm, gate g = sigmoid(mn@wg + bg),
//     out = (o[i]*g) @ wo^T + bo. Grid stride is a multiple of I so each
//     thread's i (and o[i][:]) is loop-invariant.
// ---------------------------------------------------------------------------
#define K3_BLOCKS 304   // 304*256 = 77824 = 76*1024 (multiple of I)

__global__ __launch_bounds__(256) void k3(const float* __restrict__ m,
                                          const float* __restrict__ lnw,
                                          const float* __restrict__ lnb,
                                          const float* __restrict__ wg,
                                          const float* __restrict__ bg,
                                          const float* __restrict__ wo,
                                          const float* __restrict__ bo,
                                          float* __restrict__ out)
{
    const int gt = blockIdx.x * 256 + threadIdx.x;
    const int i  = gt & (I - 1);

    float LW[C], LB[C], BG[H], BO[C], WG[H][C], WO[C][H];
#pragma unroll
    for (int c = 0; c < C; ++c) { LW[c] = lnw[c]; LB[c] = lnb[c]; BO[c] = bo[c]; }
#pragma unroll
    for (int h = 0; h < H; ++h) {
        BG[h] = bg[h];
#pragma unroll
        for (int c = 0; c < C; ++c) WG[h][c] = wg[h * C + c];
    }
#pragma unroll
    for (int c = 0; c < C; ++c)
#pragma unroll
        for (int h = 0; h < H; ++h) WO[c][h] = wo[c * H + h];

    float O[H];
#pragma unroll
    for (int h = 0; h < H; ++h) O[h] = g_o[i * H + h];

    const size_t stride = (size_t)K3_BLOCKS * 256;
    for (size_t p = gt; p < (size_t)S * I; p += stride) {
        const float4* mp = (const float4*)(m + p * C);
        float4 a = mp[0], b = mp[1];
        float x[C] = {a.x, a.y, a.z, a.w, b.x, b.y, b.z, b.w};

        float mu = 0.f;
#pragma unroll
        for (int c = 0; c < C; ++c) mu += x[c];
        mu *= (1.0f / C);
        float var = 0.f;
#pragma unroll
        for (int c = 0; c < C; ++c) { float d = x[c] - mu; var += d * d; }
        var *= (1.0f / C);
        const float rstd = rsqrtf(var + 1e-5f);

        float mn[C];
#pragma unroll
        for (int c = 0; c < C; ++c) mn[c] = (x[c] - mu) * rstd * LW[c] + LB[c];

        float acc[C];
#pragma unroll
        for (int c = 0; c < C; ++c) acc[c] = BO[c];

#pragma unroll
        for (int h = 0; h < H; ++h) {
            float z = BG[h];
#pragma unroll
            for (int c = 0; c < C; ++c) z += mn[c] * WG[h][c];
            const float g = 1.0f / (1.0f + __expf(-z));
            const float th = O[h] * g;
#pragma unroll
            for (int c = 0; c < C; ++c) acc[c] += th * WO[c][h];
        }

        float4 r0 = make_float4(acc[0], acc[1], acc[2], acc[3]);
        float4 r1 = make_float4(acc[4], acc[5], acc[6], acc[7]);
        float4* op = (float4*)(out + p * C);
        op[0] = r0;
        op[1] = r1;
    }
}

// ---------------------------------------------------------------------------
extern "C" void kernel_launch(void* const* d_in, const int* in_sizes, int n_in,
                              void* d_out, int out_size)
{
    const float* m    = (const float*)d_in[0];
    const float* mask = (const float*)d_in[1];
    const float* lnw  = (const float*)d_in[2];
    const float* lnb  = (const float*)d_in[3];
    const float* wq   = (const float*)d_in[4];
    const float* wk   = (const float*)d_in[5];
    const float* wv   = (const float*)d_in[6];
    const float* wg   = (const float*)d_in[7];
    const float* bg   = (const float*)d_in[8];
    const float* wo   = (const float*)d_in[9];
    const float* bo   = (const float*)d_in[10];
    float* out = (float*)d_out;

    dim3 g1(I / TI, NSB);
    k1<<<g1, 256>>>(m, mask, lnw, lnb, wk, wv);
    k2<<<I / 8, 256>>>(mask, wq);
    k3<<<K3_BLOCKS, 256>>>(m, lnw, lnb, wg, bg, wo, bo, out);
}

// round 3
// speedup vs baseline: 1.0161x; 1.0044x over previous
#include <cuda_runtime.h>

// Problem constants (fixed for this checkpoint)
#define S 4096
#define I 1024
#define C 8
#define H 8
#define NSB 8
#define SB (S / NSB)   // 512
#define TI 16

// Scratch (static __device__ arrays per harness rules)
__device__ float2 g_kv[S * I];            // interleaved k,v per (s,i)  ~33.5 MB
__device__ float  g_qpart[NSB * I * 9];   // per-s-block partial {qsum[8], msum}
__device__ float  g_o[I * H];             // attention output per (i,h)

// ---------------------------------------------------------------------------
// K1: per (s,i) layernorm -> k,v scalars (coalesced float2 store) + masked
//     mean-pool partials per (s_block, i). Deterministic, no atomics.
// ---------------------------------------------------------------------------
__global__ __launch_bounds__(256) void k1(const float* __restrict__ m,
                                          const float* __restrict__ mask,
                                          const float* __restrict__ lnw,
                                          const float* __restrict__ lnb,
                                          const float* __restrict__ wk,
                                          const float* __restrict__ wv)
{
    const int il = threadIdx.x & (TI - 1);
    const int sl = threadIdx.x >> 4;          // 0..15
    const int i0 = blockIdx.x * TI;
    const int s0 = blockIdx.y * SB;
    const int i  = i0 + il;

    float LW[C], LB[C], WK[C], WV[C];
#pragma unroll
    for (int c = 0; c < C; ++c) { LW[c] = lnw[c]; LB[c] = lnb[c]; WK[c] = wk[c]; WV[c] = wv[c]; }

    float qs[C];
#pragma unroll
    for (int c = 0; c < C; ++c) qs[c] = 0.f;
    float ms = 0.f;

#pragma unroll 2
    for (int j = 0; j < SB / 16; ++j) {
        const int s = s0 + sl + j * 16;
        const float4* mp = (const float4*)(m + ((size_t)s * I + i) * C);
        float4 a = mp[0], b = mp[1];
        float x[C] = {a.x, a.y, a.z, a.w, b.x, b.y, b.z, b.w};

        float mu = 0.f;
#pragma unroll
        for (int c = 0; c < C; ++c) mu += x[c];
        mu *= (1.0f / C);
        float var = 0.f;
#pragma unroll
        for (int c = 0; c < C; ++c) { float d = x[c] - mu; var += d * d; }
        var *= (1.0f / C);
        const float rstd = rsqrtf(var + 1e-5f);
        const float mk = mask[(size_t)s * I + i];

        float kk = 0.f, vv = 0.f;
#pragma unroll
        for (int c = 0; c < C; ++c) {
            float mn = (x[c] - mu) * rstd * LW[c] + LB[c];
            kk += mn * WK[c];
            vv += mn * WV[c];
            qs[c] += mn * mk;
        }
        ms += mk;
        g_kv[(size_t)s * I + i] = make_float2(kk, vv);
    }

    // reduce masked-pool partials over the 16 s-lanes per i
    __shared__ float red[16][TI][9];
#pragma unroll
    for (int c = 0; c < C; ++c) red[sl][il][c] = qs[c];
    red[sl][il][8] = ms;
    __syncthreads();

    const int t = threadIdx.x;
    if (t < TI * 9) {
        const int ril = t / 9, rc = t % 9;
        float sum = 0.f;
#pragma unroll
        for (int r = 0; r < 16; ++r) sum += red[r][ril][rc];
        g_qpart[((size_t)blockIdx.y * I + (i0 + ril)) * 9 + rc] = sum;
    }
}

// ---------------------------------------------------------------------------
// K2: per i (8 per CTA): finalize q = pooled@wq, two-pass softmax over s
//     (max pass + exp/sum pass), o[i][h] = sum(p*v)/sum(p).
//     k,v read from just-written L2-resident scratch.
// ---------------------------------------------------------------------------
__global__ __launch_bounds__(256) void k2(const float* __restrict__ mask,
                                          const float* __restrict__ wq)
{
    const int t  = threadIdx.x;
    const int i0 = blockIdx.x * 8;

    __shared__ float qp[8][9];
    __shared__ float shq[8][8];
    __shared__ float shmax[8][8];
    __shared__ float sred[256 * 16];

    if (t < 72) {
        const int il = t / 9, c = t % 9;
        float sum = 0.f;
#pragma unroll
        for (int nb = 0; nb < NSB; ++nb)
            sum += g_qpart[((size_t)nb * I + i0 + il) * 9 + c];
        qp[il][c] = sum;
    }
    __syncthreads();
    if (t < 64) {
        const int il = t >> 3, h = t & 7;
        const float inv = 1.0f / (qp[il][8] + 1e-5f);
        float q = 0.f;
#pragma unroll
        for (int c = 0; c < C; ++c) q += (qp[il][c] * inv) * wq[h * C + c];
        shq[il][h] = q;   // c_h^-0.5 = 1
    }
    __syncthreads();

    const int il = t & 7;
    const int sl = t >> 3;        // 0..31
    const int i  = i0 + il;

    float q[H];
#pragma unroll
    for (int h = 0; h < H; ++h) q[h] = shq[il][h];

    // pass A: max
    float mx[H];
#pragma unroll
    for (int h = 0; h < H; ++h) mx[h] = -1e30f;
    for (int s = sl; s < S; s += 32) {
        const float2 kv = g_kv[(size_t)s * I + i];
        const float bias = 1e9f * (mask[(size_t)s * I + i] - 1.0f);
#pragma unroll
        for (int h = 0; h < H; ++h) mx[h] = fmaxf(mx[h], q[h] * kv.x + bias);
    }
#pragma unroll
    for (int h = 0; h < H; ++h) sred[t * 8 + h] = mx[h];
    __syncthreads();
    if (t < 64) {
        const int ril = t >> 3, h = t & 7;
        float M = -1e30f;
#pragma unroll
        for (int r = 0; r < 32; ++r) M = fmaxf(M, sred[(ril + 8 * r) * 8 + h]);
        shmax[ril][h] = M;
    }
    __syncthreads();
    float M[H];
#pragma unroll
    for (int h = 0; h < H; ++h) M[h] = shmax[il][h];

    // pass B: exp/sum/weighted-v
    float sm[H], ov[H];
#pragma unroll
    for (int h = 0; h < H; ++h) { sm[h] = 0.f; ov[h] = 0.f; }
    for (int s = sl; s < S; s += 32) {
        const float2 kv = g_kv[(size_t)s * I + i];
        const float bias = 1e9f * (mask[(size_t)s * I + i] - 1.0f);
#pragma unroll
        for (int h = 0; h < H; ++h) {
            const float p = __expf(q[h] * kv.x + bias - M[h]);
            sm[h] += p;
            ov[h] += p * kv.y;
        }
    }
    __syncthreads();   // sred reuse safe: prior reads completed before shmax sync
#pragma unroll
    for (int h = 0; h < H; ++h) { sred[t * 16 + h] = sm[h]; sred[t * 16 + 8 + h] = ov[h]; }
    __syncthreads();
    if (t < 64) {
        const int ril = t >> 3, h = t & 7;
        float Ssum = 0.f, OV = 0.f;
#pragma unroll
        for (int r = 0; r < 32; ++r) {
            Ssum += sred[(ril + 8 * r) * 16 + h];
            OV   += sred[(ril + 8 * r) * 16 + 8 + h];
        }
        g_o[(i0 + ril) * H + h] = OV / Ssum;
    }
}

// ---------------------------------------------------------------------------
// K3: per (s,i): recompute layernorm, gate g = sigmoid(mn@wg + bg),
//     out = (o[i]*g) @ wo^T + bo. Grid stride is a multiple of I so each
//     thread's i (and o[i][:]) is loop-invariant.
// ---------------------------------------------------------------------------
#define K3_BLOCKS 304   // 304*256 = 77824 = 76*1024 (multiple of I)

__global__ __launch_bounds__(256) void k3(const float* __restrict__ m,
                                          const float* __restrict__ lnw,
                                          const float* __restrict__ lnb,
                                          const float* __restrict__ wg,
                                          const float* __restrict__ bg,
                                          const float* __restrict__ wo,
                                          const float* __restrict__ bo,
                                          float* __restrict__ out)
{
    const int gt = blockIdx.x * 256 + threadIdx.x;
    const int i  = gt & (I - 1);

    float LW[C], LB[C], BG[H], BO[C], WG[H][C], WO[C][H];
#pragma unroll
    for (int c = 0; c < C; ++c) { LW[c] = lnw[c]; LB[c] = lnb[c]; BO[c] = bo[c]; }
#pragma unroll
    for (int h = 0; h < H; ++h) {
        BG[h] = bg[h];
#pragma unroll
        for (int c = 0; c < C; ++c) WG[h][c] = wg[h * C + c];
    }
#pragma unroll
    for (int c = 0; c < C; ++c)
#pragma unroll
        for (int h = 0; h < H; ++h) WO[c][h] = wo[c * H + h];

    float O[H];
#pragma unroll
    for (int h = 0; h < H; ++h) O[h] = g_o[i * H + h];

    const size_t stride = (size_t)K3_BLOCKS * 256;
    for (size_t p = gt; p < (size_t)S * I; p += stride) {
        const float4* mp = (const float4*)(m + p * C);
        float4 a = mp[0], b = mp[1];
        float x[C] = {a.x, a.y, a.z, a.w, b.x, b.y, b.z, b.w};

        float mu = 0.f;
#pragma unroll
        for (int c = 0; c < C; ++c) mu += x[c];
        mu *= (1.0f / C);
        float var = 0.f;
#pragma unroll
        for (int c = 0; c < C; ++c) { float d = x[c] - mu; var += d * d; }
        var *= (1.0f / C);
        const float rstd = rsqrtf(var + 1e-5f);

        float mn[C];
#pragma unroll
        for (int c = 0; c < C; ++c) mn[c] = (x[c] - mu) * rstd * LW[c] + LB[c];

        float acc[C];
#pragma unroll
        for (int c = 0; c < C; ++c) acc[c] = BO[c];

#pragma unroll
        for (int h = 0; h < H; ++h) {
            float z = BG[h];
#pragma unroll
            for (int c = 0; c < C; ++c) z += mn[c] * WG[h][c];
            const float g = 1.0f / (1.0f + __expf(-z));
            const float th = O[h] * g;
#pragma unroll
            for (int c = 0; c < C; ++c) acc[c] += th * WO[c][h];
        }

        float4 r0 = make_float4(acc[0], acc[1], acc[2], acc[3]);
        float4 r1 = make_float4(acc[4], acc[5], acc[6], acc[7]);
        float4* op = (float4*)(out + p * C);
        op[0] = r0;
        op[1] = r1;
    }
}

// ---------------------------------------------------------------------------
extern "C" void kernel_launch(void* const* d_in, const int* in_sizes, int n_in,
                              void* d_out, int out_size)
{
    const float* m    = (const float*)d_in[0];
    const float* mask = (const float*)d_in[1];
    const float* lnw  = (const float*)d_in[2];
    const float* lnb  = (const float*)d_in[3];
    const float* wq   = (const float*)d_in[4];
    const float* wk   = (const float*)d_in[5];
    const float* wv   = (const float*)d_in[6];
    const float* wg   = (const float*)d_in[7];
    const float* bg   = (const float*)d_in[8];
    const float* wo   = (const float*)d_in[9];
    const float* bo   = (const float*)d_in[10];
    float* out = (float*)d_out;

    dim3 g1(I / TI, NSB);
    k1<<<g1, 256>>>(m, mask, lnw, lnb, wk, wv);
    k2<<<I / 8, 256>>>(mask, wq);
    k3<<<K3_BLOCKS, 256>>>(m, lnw, lnb, wg, bg, wo, bo, out);
}

// round 4
// speedup vs baseline: 1.2390x; 1.2194x over previous
#include <cuda_runtime.h>

// Problem constants (fixed for this checkpoint)
#define S 4096
#define I 1024
#define C 8
#define H 8
#define NSB 16           // k1 s-blocks
#define SB (S / NSB)     // 256
#define TI 16
#define NSPLIT 8         // k2 s-splits
#define SSPL (S / NSPLIT) // 512

// Scratch (static __device__ arrays per harness rules)
__device__ float2 g_kv[S * I];               // (k,v) per (s,i)  ~33.5 MB
__device__ float  g_qpart[NSB * I * 9];      // per-s-block {qsum[8], msum}
__device__ float4 g_part[I * H * NSPLIT];    // per-split softmax partials (m,sm,ov)
__device__ float  g_o[I * H];                // attention output per (i,h)

// ---------------------------------------------------------------------------
// K1: per (s,i) layernorm -> k,v (coalesced float2 store) + masked mean-pool
//     partials. 4-way batched loads for MLP. LN folded into k/v weights.
// ---------------------------------------------------------------------------
__global__ __launch_bounds__(256) void k1(const float* __restrict__ m,
                                          const float* __restrict__ mask,
                                          const float* __restrict__ lnw,
                                          const float* __restrict__ lnb,
                                          const float* __restrict__ wk,
                                          const float* __restrict__ wv)
{
    const int il = threadIdx.x & (TI - 1);
    const int sl = threadIdx.x >> 4;          // 0..15
    const int i0 = blockIdx.x * TI;
    const int s0 = blockIdx.y * SB;
    const int i  = i0 + il;

    // Folded weights: k = rstd*(WKf.x - mu*WKs) + WKb   (WKf = wk*lnw)
    float LW[C], LB[C], WKf[C], WVf[C];
    float WKs = 0.f, WVs = 0.f, WKb = 0.f, WVb = 0.f;
#pragma unroll
    for (int c = 0; c < C; ++c) {
        LW[c] = lnw[c]; LB[c] = lnb[c];
        WKf[c] = wk[c] * LW[c]; WVf[c] = wv[c] * LW[c];
        WKs += WKf[c]; WVs += WVf[c];
        WKb += wk[c] * LB[c]; WVb += wv[c] * LB[c];
    }

    float qs[C];
#pragma unroll
    for (int c = 0; c < C; ++c) qs[c] = 0.f;
    float ms = 0.f;

    for (int jb = 0; jb < SB / 16 / 4; ++jb) {
        float4 a[4], b[4]; float mk[4]; int sArr[4];
#pragma unroll
        for (int u = 0; u < 4; ++u) {
            const int s = s0 + sl + (jb * 4 + u) * 16;
            sArr[u] = s;
            const float4* mp = (const float4*)(m + ((size_t)s * I + i) * C);
            a[u] = mp[0]; b[u] = mp[1];
            mk[u] = mask[(size_t)s * I + i];
        }
#pragma unroll
        for (int u = 0; u < 4; ++u) {
            float x[C] = {a[u].x, a[u].y, a[u].z, a[u].w, b[u].x, b[u].y, b[u].z, b[u].w};
            float mu = 0.f;
#pragma unroll
            for (int c = 0; c < C; ++c) mu += x[c];
            mu *= (1.0f / C);
            float var = 0.f;
#pragma unroll
            for (int c = 0; c < C; ++c) { float d = x[c] - mu; var += d * d; }
            var *= (1.0f / C);
            const float rstd = rsqrtf(var + 1e-5f);

            float dk = 0.f, dv = 0.f;
#pragma unroll
            for (int c = 0; c < C; ++c) { dk += WKf[c] * x[c]; dv += WVf[c] * x[c]; }
            const float kk = rstd * (dk - mu * WKs) + WKb;
            const float vv = rstd * (dv - mu * WVs) + WVb;

            const float mkr = mk[u] * rstd;
#pragma unroll
            for (int c = 0; c < C; ++c)
                qs[c] += (LW[c] * ((x[c] - mu) * mkr)) + LB[c] * mk[u];
            ms += mk[u];
            g_kv[(size_t)sArr[u] * I + i] = make_float2(kk, vv);
        }
    }

    __shared__ float red[16][TI][9];
#pragma unroll
    for (int c = 0; c < C; ++c) red[sl][il][c] = qs[c];
    red[sl][il][8] = ms;
    __syncthreads();

    const int t = threadIdx.x;
    if (t < TI * 9) {
        const int ril = t / 9, rc = t % 9;
        float sum = 0.f;
#pragma unroll
        for (int r = 0; r < 16; ++r) sum += red[r][ril][rc];
        g_qpart[((size_t)blockIdx.y * I + (i0 + ril)) * 9 + rc] = sum;
    }
}

// ---------------------------------------------------------------------------
// K2: split-s softmax. Grid (I/8, NSPLIT). Each CTA: 8 i's x 512 s's.
//     Each thread keeps its 16 (k,v,bias) in registers across both passes.
//     Writes per-split (max, sum, ov) partials.
// ---------------------------------------------------------------------------
__global__ __launch_bounds__(256) void k2(const float* __restrict__ mask,
                                          const float* __restrict__ wq)
{
    const int t  = threadIdx.x;
    const int i0 = blockIdx.x * 8;
    const int sp = blockIdx.y;
    const int s0 = sp * SSPL;

    __shared__ float qp[8][9];
    __shared__ float shq[8][8];
    __shared__ float shmax[8][8];
    __shared__ float sred[256 * 16];

    if (t < 72) {
        const int il = t / 9, c = t % 9;
        float sum = 0.f;
#pragma unroll
        for (int nb = 0; nb < NSB; ++nb)
            sum += g_qpart[((size_t)nb * I + i0 + il) * 9 + c];
        qp[il][c] = sum;
    }
    __syncthreads();
    if (t < 64) {
        const int il = t >> 3, h = t & 7;
        const float inv = 1.0f / (qp[il][8] + 1e-5f);
        float q = 0.f;
#pragma unroll
        for (int c = 0; c < C; ++c) q += (qp[il][c] * inv) * wq[h * C + c];
        shq[il][h] = q;   // c_h^-0.5 = 1
    }
    __syncthreads();

    const int il = t & 7;
    const int sl = t >> 3;        // 0..31
    const int i  = i0 + il;

    float q[H];
#pragma unroll
    for (int h = 0; h < H; ++h) q[h] = shq[il][h];

    // load 16 (k,v,bias) into registers, front-batched
    float kr[16], vr[16], br[16];
#pragma unroll
    for (int j = 0; j < 16; ++j) {
        const int s = s0 + sl + j * 32;
        const float2 kv = g_kv[(size_t)s * I + i];
        kr[j] = kv.x; vr[j] = kv.y;
        br[j] = 1e9f * (mask[(size_t)s * I + i] - 1.0f);
    }

    // pass A: per-thread max
    float mx[H];
#pragma unroll
    for (int h = 0; h < H; ++h) mx[h] = -1e30f;
#pragma unroll
    for (int j = 0; j < 16; ++j)
#pragma unroll
        for (int h = 0; h < H; ++h) mx[h] = fmaxf(mx[h], q[h] * kr[j] + br[j]);

#pragma unroll
    for (int h = 0; h < H; ++h) sred[t * 8 + h] = mx[h];
    __syncthreads();
    if (t < 64) {
        const int ril = t >> 3, h = t & 7;
        float M = -1e30f;
#pragma unroll
        for (int r = 0; r < 32; ++r) M = fmaxf(M, sred[(ril + 8 * r) * 8 + h]);
        shmax[ril][h] = M;
    }
    __syncthreads();
    float M[H];
#pragma unroll
    for (int h = 0; h < H; ++h) M[h] = shmax[il][h];

    // pass B: exp / sum / weighted-v from registers
    float sm[H], ov[H];
#pragma unroll
    for (int h = 0; h < H; ++h) { sm[h] = 0.f; ov[h] = 0.f; }
#pragma unroll
    for (int j = 0; j < 16; ++j)
#pragma unroll
        for (int h = 0; h < H; ++h) {
            const float p = __expf(q[h] * kr[j] + br[j] - M[h]);
            sm[h] += p;
            ov[h] += p * vr[j];
        }

    __syncthreads();
#pragma unroll
    for (int h = 0; h < H; ++h) { sred[t * 16 + h] = sm[h]; sred[t * 16 + 8 + h] = ov[h]; }
    __syncthreads();
    if (t < 64) {
        const int ril = t >> 3, h = t & 7;
        float Ssum = 0.f, OV = 0.f;
#pragma unroll
        for (int r = 0; r < 32; ++r) {
            Ssum += sred[(ril + 8 * r) * 16 + h];
            OV   += sred[(ril + 8 * r) * 16 + 8 + h];
        }
        g_part[((size_t)(i0 + ril) * H + h) * NSPLIT + sp] =
            make_float4(shmax[ril][h], Ssum, OV, 0.f);
    }
}

// ---------------------------------------------------------------------------
// K2b: combine split partials -> g_o. One thread per (i,h).
// ---------------------------------------------------------------------------
__global__ __launch_bounds__(256) void k2b()
{
    const int id = blockIdx.x * 256 + threadIdx.x;   // 0..8191
    float4 p[NSPLIT];
#pragma unroll
    for (int sp = 0; sp < NSPLIT; ++sp) p[sp] = g_part[(size_t)id * NSPLIT + sp];

    float G = -1e30f;
#pragma unroll
    for (int sp = 0; sp < NSPLIT; ++sp) G = fmaxf(G, p[sp].x);
    float Ssum = 0.f, OV = 0.f;
#pragma unroll
    for (int sp = 0; sp < NSPLIT; ++sp) {
        const float w = __expf(p[sp].x - G);
        Ssum += p[sp].y * w;
        OV   += p[sp].z * w;
    }
    g_o[id] = OV / Ssum;
}

// ---------------------------------------------------------------------------
// K3: per (s,i): recompute LN stats, gate, out = (o[i]*g)@wo^T + bo.
//     Weights live in SMEM (warp-uniform broadcast); LN folded into gate
//     weights so only mu/rstd are needed per point. Single wave: 512 CTAs,
//     stride 131072 (multiple of I) -> i loop-invariant, exactly 32 iters.
// ---------------------------------------------------------------------------
#define K3_BLOCKS 512
#define K3_STRIDE (K3_BLOCKS * 256)   // 131072

__global__ __launch_bounds__(256) void k3(const float* __restrict__ m,
                                          const float* __restrict__ lnw,
                                          const float* __restrict__ lnb,
                                          const float* __restrict__ wg,
                                          const float* __restrict__ bg,
                                          const float* __restrict__ wo,
                                          const float* __restrict__ bo,
                                          float* __restrict__ out)
{
    __shared__ float sWGf[H][C];   // wg * lnw
    __shared__ float sWGs[H];      // row sums of sWGf
    __shared__ float sBGf[H];      // bg + wg@lnb
    __shared__ float sWO[C][H];
    __shared__ float sBO[C];

    const int t = threadIdx.x;
    if (t < H) {
        const int h = t;
        float rs = 0.f, bb = bg[h];
#pragma unroll
        for (int c = 0; c < C; ++c) {
            const float w = wg[h * C + c];
            const float wf = w * lnw[c];
            sWGf[h][c] = wf;
            rs += wf;
            bb += w * lnb[c];
        }
        sWGs[h] = rs;
        sBGf[h] = bb;
    }
    if (t >= 64 && t < 128) {
        const int id = t - 64;
        sWO[id >> 3][id & 7] = wo[id];
    }
    if (t >= 128 && t < 136) sBO[t - 128] = bo[t - 128];
    __syncthreads();

    const int gt = blockIdx.x * 256 + t;
    const int i  = gt & (I - 1);

    float O[H];
#pragma unroll
    for (int h = 0; h < H; ++h) O[h] = g_o[i * H + h];

    for (int it = 0; it < 16; ++it) {
        const size_t p0 = (size_t)gt + (size_t)(2 * it) * K3_STRIDE;
        float4 a[2], b[2];
#pragma unroll
        for (int u = 0; u < 2; ++u) {
            const float4* mp = (const float4*)(m + (p0 + (size_t)u * K3_STRIDE) * C);
            a[u] = mp[0]; b[u] = mp[1];
        }
#pragma unroll
        for (int u = 0; u < 2; ++u) {
            float x[C] = {a[u].x, a[u].y, a[u].z, a[u].w, b[u].x, b[u].y, b[u].z, b[u].w};
            float mu = 0.f;
#pragma unroll
            for (int c = 0; c < C; ++c) mu += x[c];
            mu *= (1.0f / C);
            float var = 0.f;
#pragma unroll
            for (int c = 0; c < C; ++c) { float d = x[c] - mu; var += d * d; }
            var *= (1.0f / C);
            const float rstd = rsqrtf(var + 1e-5f);
            const float murs = mu * rstd;

            float gO[H];
#pragma unroll
            for (int h = 0; h < H; ++h) {
                float d = 0.f;
#pragma unroll
                for (int c = 0; c < C; ++c) d += sWGf[h][c] * x[c];
                const float z = fmaf(rstd, d, fmaf(-murs, sWGs[h], sBGf[h]));
                const float g = 1.0f / (1.0f + __expf(-z));
                gO[h] = g * O[h];
            }

            float acc[C];
#pragma unroll
            for (int c = 0; c < C; ++c) acc[c] = sBO[c];
#pragma unroll
            for (int h = 0; h < H; ++h)
#pragma unroll
                for (int c = 0; c < C; ++c) acc[c] += gO[h] * sWO[c][h];

            float4* op = (float4*)(out + (p0 + (size_t)u * K3_STRIDE) * C);
            op[0] = make_float4(acc[0], acc[1], acc[2], acc[3]);
            op[1] = make_float4(acc[4], acc[5], acc[6], acc[7]);
        }
    }
}

// ---------------------------------------------------------------------------
extern "C" void kernel_launch(void* const* d_in, const int* in_sizes, int n_in,
                              void* d_out, int out_size)
{
    const float* m    = (const float*)d_in[0];
    const float* mask = (const float*)d_in[1];
    const float* lnw  = (const float*)d_in[2];
    const float* lnb  = (const float*)d_in[3];
    const float* wq   = (const float*)d_in[4];
    const float* wk   = (const float*)d_in[5];
    const float* wv   = (const float*)d_in[6];
    const float* wg   = (const float*)d_in[7];
    const float* bg   = (const float*)d_in[8];
    const float* wo   = (const float*)d_in[9];
    const float* bo   = (const float*)d_in[10];
    float* out = (float*)d_out;

    dim3 g1(I / TI, NSB);
    k1<<<g1, 256>>>(m, mask, lnw, lnb, wk, wv);
    dim3 g2(I / 8, NSPLIT);
    k2<<<g2, 256>>>(mask, wq);
    k2b<<<(I * H) / 256, 256>>>();
    k3<<<K3_BLOCKS, 256>>>(m, lnw, lnb, wg, bg, wo, bo, out);
}

// round 5
// speedup vs baseline: 1.6813x; 1.3570x over previous
#include <cuda_runtime.h>

// Problem constants (fixed for this checkpoint)
#define S 4096
#define I 1024
#define C 8
#define H 8
#define NSB 16            // k1 s-blocks
#define SB (S / NSB)      // 256
#define TI 16
#define NSPLIT 16         // k2 s-splits
#define SSPL (S / NSPLIT) // 256

// Scratch (static __device__ arrays per harness rules)
__device__ float2 g_kv[S * I];               // (k,v) per (s,i)  ~33.5 MB
__device__ float  g_qpart[NSB * I * 9];      // per-s-block {qsum[8], msum}
__device__ float4 g_part[I * H * NSPLIT];    // per-split softmax partials (m,sm,ov)
__device__ float  g_o[I * H];                // attention output per (i,h)

// ---- f32x2 packed helpers (Blackwell FFMA2; only reachable via PTX) -------
typedef unsigned long long u64;
__device__ __forceinline__ u64 pk2(float lo, float hi) {
    u64 r; asm("mov.b64 %0, {%1,%2};" : "=l"(r) : "f"(lo), "f"(hi)); return r;
}
__device__ __forceinline__ float2 upk2(u64 v) {
    float2 f; asm("mov.b64 {%0,%1}, %2;" : "=f"(f.x), "=f"(f.y) : "l"(v)); return f;
}
#define FMA2(d, a, b, c) asm("fma.rn.f32x2 %0, %1, %2, %3;" : "=l"(d) : "l"(a), "l"(b), "l"(c))

// ---------------------------------------------------------------------------
// K1: per (s,i) layernorm -> k,v (coalesced float2 store) + masked mean-pool
//     partials. 4-way batched loads. LN folded into k/v weights.
// ---------------------------------------------------------------------------
__global__ __launch_bounds__(256) void k1(const float* __restrict__ m,
                                          const float* __restrict__ mask,
                                          const float* __restrict__ lnw,
                                          const float* __restrict__ lnb,
                                          const float* __restrict__ wk,
                                          const float* __restrict__ wv)
{
    const int il = threadIdx.x & (TI - 1);
    const int sl = threadIdx.x >> 4;          // 0..15
    const int i0 = blockIdx.x * TI;
    const int s0 = blockIdx.y * SB;
    const int i  = i0 + il;

    float LW[C], LB[C], WKf[C], WVf[C];
    float WKs = 0.f, WVs = 0.f, WKb = 0.f, WVb = 0.f;
#pragma unroll
    for (int c = 0; c < C; ++c) {
        LW[c] = lnw[c]; LB[c] = lnb[c];
        WKf[c] = wk[c] * LW[c]; WVf[c] = wv[c] * LW[c];
        WKs += WKf[c]; WVs += WVf[c];
        WKb += wk[c] * LB[c]; WVb += wv[c] * LB[c];
    }

    float qs[C];
#pragma unroll
    for (int c = 0; c < C; ++c) qs[c] = 0.f;
    float ms = 0.f;

    for (int jb = 0; jb < SB / 16 / 4; ++jb) {
        float4 a[4], b[4]; float mk[4]; int sArr[4];
#pragma unroll
        for (int u = 0; u < 4; ++u) {
            const int s = s0 + sl + (jb * 4 + u) * 16;
            sArr[u] = s;
            const float4* mp = (const float4*)(m + ((size_t)s * I + i) * C);
            a[u] = mp[0]; b[u] = mp[1];
            mk[u] = mask[(size_t)s * I + i];
        }
#pragma unroll
        for (int u = 0; u < 4; ++u) {
            float x[C] = {a[u].x, a[u].y, a[u].z, a[u].w, b[u].x, b[u].y, b[u].z, b[u].w};
            float mu = 0.f;
#pragma unroll
            for (int c = 0; c < C; ++c) mu += x[c];
            mu *= (1.0f / C);
            float var = 0.f;
#pragma unroll
            for (int c = 0; c < C; ++c) { float d = x[c] - mu; var += d * d; }
            var *= (1.0f / C);
            const float rstd = rsqrtf(var + 1e-5f);

            float dk = 0.f, dv = 0.f;
#pragma unroll
            for (int c = 0; c < C; ++c) { dk += WKf[c] * x[c]; dv += WVf[c] * x[c]; }
            const float kk = rstd * (dk - mu * WKs) + WKb;
            const float vv = rstd * (dv - mu * WVs) + WVb;

            const float mkr = mk[u] * rstd;
#pragma unroll
            for (int c = 0; c < C; ++c)
                qs[c] += (LW[c] * ((x[c] - mu) * mkr)) + LB[c] * mk[u];
            ms += mk[u];
            g_kv[(size_t)sArr[u] * I + i] = make_float2(kk, vv);
        }
    }

    __shared__ float red[16][TI][9];
#pragma unroll
    for (int c = 0; c < C; ++c) red[sl][il][c] = qs[c];
    red[sl][il][8] = ms;
    __syncthreads();

    const int t = threadIdx.x;
    if (t < TI * 9) {
        const int ril = t / 9, rc = t % 9;
        float sum = 0.f;
#pragma unroll
        for (int r = 0; r < 16; ++r) sum += red[r][ril][rc];
        g_qpart[((size_t)blockIdx.y * I + (i0 + ril)) * 9 + rc] = sum;
    }
}

// ---------------------------------------------------------------------------
// K2: split-s softmax. Grid (I/8, NSPLIT). Each CTA: 8 i's x 256 s's.
//     Thread keeps its 8 (k,v,bias) in registers across both passes.
// ---------------------------------------------------------------------------
__global__ __launch_bounds__(256) void k2(const float* __restrict__ mask,
                                          const float* __restrict__ wq)
{
    const int t  = threadIdx.x;
    const int i0 = blockIdx.x * 8;
    const int sp = blockIdx.y;
    const int s0 = sp * SSPL;

    __shared__ float qp[8][9];
    __shared__ float shq[8][8];
    __shared__ float shmax[8][8];
    __shared__ float sred[256 * 16];

    if (t < 72) {
        const int il = t / 9, c = t % 9;
        float sum = 0.f;
#pragma unroll
        for (int nb = 0; nb < NSB; ++nb)
            sum += g_qpart[((size_t)nb * I + i0 + il) * 9 + c];
        qp[il][c] = sum;
    }
    __syncthreads();
    if (t < 64) {
        const int il = t >> 3, h = t & 7;
        const float inv = 1.0f / (qp[il][8] + 1e-5f);
        float q = 0.f;
#pragma unroll
        for (int c = 0; c < C; ++c) q += (qp[il][c] * inv) * wq[h * C + c];
        shq[il][h] = q;   // c_h^-0.5 = 1
    }
    __syncthreads();

    const int il = t & 7;
    const int sl = t >> 3;        // 0..31
    const int i  = i0 + il;

    float q[H];
#pragma unroll
    for (int h = 0; h < H; ++h) q[h] = shq[il][h];

    // load 8 (k,v,bias) into registers, front-batched
    float kr[8], vr[8], br[8];
#pragma unroll
    for (int j = 0; j < 8; ++j) {
        const int s = s0 + sl + j * 32;
        const float2 kv = g_kv[(size_t)s * I + i];
        kr[j] = kv.x; vr[j] = kv.y;
        br[j] = 1e9f * (mask[(size_t)s * I + i] - 1.0f);
    }

    // pass A: per-thread max
    float mx[H];
#pragma unroll
    for (int h = 0; h < H; ++h) mx[h] = -1e30f;
#pragma unroll
    for (int j = 0; j < 8; ++j)
#pragma unroll
        for (int h = 0; h < H; ++h) mx[h] = fmaxf(mx[h], q[h] * kr[j] + br[j]);

#pragma unroll
    for (int h = 0; h < H; ++h) sred[t * 8 + h] = mx[h];
    __syncthreads();
    if (t < 64) {
        const int ril = t >> 3, h = t & 7;
        float M = -1e30f;
#pragma unroll
        for (int r = 0; r < 32; ++r) M = fmaxf(M, sred[(ril + 8 * r) * 8 + h]);
        shmax[ril][h] = M;
    }
    __syncthreads();
    float M[H];
#pragma unroll
    for (int h = 0; h < H; ++h) M[h] = shmax[il][h];

    // pass B: exp / sum / weighted-v from registers
    float sm[H], ov[H];
#pragma unroll
    for (int h = 0; h < H; ++h) { sm[h] = 0.f; ov[h] = 0.f; }
#pragma unroll
    for (int j = 0; j < 8; ++j)
#pragma unroll
        for (int h = 0; h < H; ++h) {
            const float p = __expf(q[h] * kr[j] + br[j] - M[h]);
            sm[h] += p;
            ov[h] += p * vr[j];
        }

    __syncthreads();
#pragma unroll
    for (int h = 0; h < H; ++h) { sred[t * 16 + h] = sm[h]; sred[t * 16 + 8 + h] = ov[h]; }
    __syncthreads();
    if (t < 64) {
        const int ril = t >> 3, h = t & 7;
        float Ssum = 0.f, OV = 0.f;
#pragma unroll
        for (int r = 0; r < 32; ++r) {
            Ssum += sred[(ril + 8 * r) * 16 + h];
            OV   += sred[(ril + 8 * r) * 16 + 8 + h];
        }
        g_part[((size_t)(i0 + ril) * H + h) * NSPLIT + sp] =
            make_float4(shmax[ril][h], Ssum, OV, 0.f);
    }
}

// ---------------------------------------------------------------------------
// K2b: combine split partials -> g_o. One thread per (i,h).
// ---------------------------------------------------------------------------
__global__ __launch_bounds__(256) void k2b()
{
    const int id = blockIdx.x * 256 + threadIdx.x;   // 0..8191
    float4 p[NSPLIT];
#pragma unroll
    for (int sp = 0; sp < NSPLIT; ++sp) p[sp] = g_part[(size_t)id * NSPLIT + sp];

    float G = -1e30f;
#pragma unroll
    for (int sp = 0; sp < NSPLIT; ++sp) G = fmaxf(G, p[sp].x);
    float Ssum = 0.f, OV = 0.f;
#pragma unroll
    for (int sp = 0; sp < NSPLIT; ++sp) {
        const float w = __expf(p[sp].x - G);
        Ssum += p[sp].y * w;
        OV   += p[sp].z * w;
    }
    g_o[id] = OV / Ssum;
}

// ---------------------------------------------------------------------------
// K3: per (s,i): LN stats, gate, out = (o[i]*g)@wo^T + bo.
//     f32x2 packed FFMA2 for both 8x8 matvecs; O folded into WO per thread.
//     Grid 1024 CTAs, stride 262144 (multiple of I) -> i loop-invariant,
//     exactly 16 points/thread, batched 4 (8 LDG.128 in flight).
// ---------------------------------------------------------------------------
#define K3_BLOCKS 1024
#define K3_STRIDE (K3_BLOCKS * 256)   // 262144

__global__ __launch_bounds__(256) void k3(const float* __restrict__ m,
                                          const float* __restrict__ lnw,
                                          const float* __restrict__ lnb,
                                          const float* __restrict__ wg,
                                          const float* __restrict__ bg,
                                          const float* __restrict__ wo,
                                          const float* __restrict__ bo,
                                          float* __restrict__ out)
{
    const int t  = threadIdx.x;
    const int gt = blockIdx.x * 256 + t;
    const int i  = gt & (I - 1);

    // ---- build folded, packed weights in registers ----
    float LWr[C], LBr[C];
#pragma unroll
    for (int c = 0; c < C; ++c) { LWr[c] = __ldg(lnw + c); LBr[c] = __ldg(lnb + c); }

    float WGf[H][C], WGs[H], BGf[H];
#pragma unroll
    for (int h = 0; h < H; ++h) {
        float rs = 0.f, bb = __ldg(bg + h);
#pragma unroll
        for (int c = 0; c < C; ++c) {
            const float w = __ldg(wg + h * C + c);
            WGf[h][c] = w * LWr[c];
            rs += WGf[h][c];
            bb += w * LBr[c];
        }
        WGs[h] = rs; BGf[h] = bb;
    }

    float O[H];
#pragma unroll
    for (int h = 0; h < H; ++h) O[h] = g_o[i * H + h];

    // WG2[p][c] = (WGf[2p][c], WGf[2p+1][c])  (head pairs)
    u64 WG2[4][C], WGs2[4], BGf2[4];
#pragma unroll
    for (int p = 0; p < 4; ++p) {
#pragma unroll
        for (int c = 0; c < C; ++c) WG2[p][c] = pk2(WGf[2 * p][c], WGf[2 * p + 1][c]);
        WGs2[p] = pk2(-WGs[2 * p], -WGs[2 * p + 1]);
        BGf2[p] = pk2(BGf[2 * p], BGf[2 * p + 1]);
    }
    // WO2[q][h] = (O[h]*wo[2q][h], O[h]*wo[2q+1][h])  (c pairs)
    u64 WO2[4][H], BO2[4];
#pragma unroll
    for (int q = 0; q < 4; ++q) {
#pragma unroll
        for (int h = 0; h < H; ++h)
            WO2[q][h] = pk2(O[h] * __ldg(wo + (2 * q) * H + h),
                            O[h] * __ldg(wo + (2 * q + 1) * H + h));
        BO2[q] = pk2(__ldg(bo + 2 * q), __ldg(bo + 2 * q + 1));
    }

    for (int it = 0; it < 4; ++it) {
        const size_t p0 = (size_t)gt + (size_t)(4 * it) * K3_STRIDE;
        float4 a[4], b[4];
#pragma unroll
        for (int u = 0; u < 4; ++u) {
            const float4* mp = (const float4*)(m + (p0 + (size_t)u * K3_STRIDE) * C);
            a[u] = mp[0]; b[u] = mp[1];
        }
#pragma unroll
        for (int u = 0; u < 4; ++u) {
            float x[C] = {a[u].x, a[u].y, a[u].z, a[u].w, b[u].x, b[u].y, b[u].z, b[u].w};
            float mu = 0.f;
#pragma unroll
            for (int c = 0; c < C; ++c) mu += x[c];
            mu *= (1.0f / C);
            float var = 0.f;
#pragma unroll
            for (int c = 0; c < C; ++c) { float d = x[c] - mu; var += d * d; }
            var *= (1.0f / C);
            const float rstd = rsqrtf(var + 1e-5f);
            const float murs = mu * rstd;

            u64 xd[C];
#pragma unroll
            for (int c = 0; c < C; ++c) xd[c] = pk2(x[c], x[c]);

            const u64 rstd2 = pk2(rstd, rstd);
            const u64 murs2 = pk2(murs, murs);

            // gate: z2[p] = rstd*(WGf.x) - murs*WGs + BGf
            u64 z2[4];
#pragma unroll
            for (int p = 0; p < 4; ++p) {
                u64 D = 0;
                FMA2(D, xd[0], WG2[p][0], D);
#pragma unroll
                for (int c = 1; c < C; ++c) FMA2(D, xd[c], WG2[p][c], D);
                u64 T; FMA2(T, murs2, WGs2[p], BGf2[p]);   // WGs2 pre-negated
                FMA2(z2[p], rstd2, D, T);
            }

            // sigmoid per head, repack duplicated
            u64 gd[H / 1];
            u64 gd2[H];
#pragma unroll
            for (int p = 0; p < 4; ++p) {
                const float2 z = upk2(z2[p]);
                const float s0v = __fdividef(1.0f, 1.0f + __expf(-z.x));
                const float s1v = __fdividef(1.0f, 1.0f + __expf(-z.y));
                gd2[2 * p]     = pk2(s0v, s0v);
                gd2[2 * p + 1] = pk2(s1v, s1v);
            }
            (void)gd;

            // output: acc2[q] = BO2[q] + sum_h gd2[h]*WO2[q][h]
            u64 acc2[4];
#pragma unroll
            for (int q = 0; q < 4; ++q) {
                u64 A = BO2[q];
#pragma unroll
                for (int h = 0; h < H; ++h) FMA2(A, gd2[h], WO2[q][h], A);
                acc2[q] = A;
            }

            const float2 r0 = upk2(acc2[0]), r1 = upk2(acc2[1]);
            const float2 r2 = upk2(acc2[2]), r3 = upk2(acc2[3]);
            float4* op = (float4*)(out + (p0 + (size_t)u * K3_STRIDE) * C);
            op[0] = make_float4(r0.x, r0.y, r1.x, r1.y);
            op[1] = make_float4(r2.x, r2.y, r3.x, r3.y);
        }
    }
}

// ---------------------------------------------------------------------------
extern "C" void kernel_launch(void* const* d_in, const int* in_sizes, int n_in,
                              void* d_out, int out_size)
{
    const float* m    = (const float*)d_in[0];
    const float* mask = (const float*)d_in[1];
    const float* lnw  = (const float*)d_in[2];
    const float* lnb  = (const float*)d_in[3];
    const float* wq   = (const float*)d_in[4];
    const float* wk   = (const float*)d_in[5];
    const float* wv   = (const float*)d_in[6];
    const float* wg   = (const float*)d_in[7];
    const float* bg   = (const float*)d_in[8];
    const float* wo   = (const float*)d_in[9];
    const float* bo   = (const float*)d_in[10];
    float* out = (float*)d_out;

    dim3 g1(I / TI, NSB);
    k1<<<g1, 256>>>(m, mask, lnw, lnb, wk, wv);
    dim3 g2(I / 8, NSPLIT);
    k2<<<g2, 256>>>(mask, wq);
    k2b<<<(I * H) / 256, 256>>>();
    k3<<<K3_BLOCKS, 256>>>(m, lnw, lnb, wg, bg, wo, bo, out);
}